// round 3
// baseline (speedup 1.0000x reference)
#include <cuda_runtime.h>
#include <cstdint>

#define NB 2
#define NC 128
#define NU 2048
#define KF 512
#define NZK 64
#define NT 32768
#define CAP (1<<18)

static __device__ float g_bufA[NB*NC*NT];
static __device__ float g_bufB[NB*NC*NT];
static __device__ float g_Wt[12*256*128];      // [layer][k=2*ci+tap][cout]
static __device__ float g_upwT[128*2048];      // [c][u]
static __device__ float g_ysub[NB*2048*512];
static __device__ float g_thresh[NB];
static __device__ int   g_candCnt[NB];
static __device__ float g_candVal[NB*CAP];
static __device__ unsigned g_candPack[NB*CAP];
static __device__ float g_selVal[NB*NZK];
static __device__ int   g_selU[NB*NZK];
static __device__ int   g_selT[NB*NZK];

// ---------------- weight transposes ----------------
__global__ void k_wt(const float* __restrict__ enc_w, const float* __restrict__ dec_w) {
    int idx = blockIdx.x * 256 + threadIdx.x;
    if (idx >= 12 * 256 * 128) return;
    int l = idx / 32768;
    int r = idx - l * 32768;
    int k = r >> 7, c = r & 127;
    int ci = k >> 1, tap = k & 1;
    const float* w = (l < 6) ? (enc_w + l * 32768) : (dec_w + (l - 6) * 32768);
    g_Wt[idx] = w[(c * 128 + ci) * 2 + tap];
}

__global__ void k_upwT(const float* __restrict__ up_w) {
    int idx = blockIdx.x * 256 + threadIdx.x;
    if (idx >= 128 * 2048) return;
    int c = idx >> 11, u = idx & 2047;
    g_upwT[idx] = up_w[u * 128 + c];
}

// ---------------- filterbank analysis: bufA = conv(x, fb) ----------------
__global__ void __launch_bounds__(256) k_fb(const float* __restrict__ x,
                                            const float* __restrict__ fb) {
    __shared__ float xs[640];
    int b = blockIdx.y, t0 = blockIdx.x * 128;
    int tid = threadIdx.x;
    for (int w = tid; w < 639; w += 256) {
        int g = t0 - 256 + w;
        xs[w] = (g >= 0 && g < NT) ? x[b * NT + g] : 0.f;
    }
    __syncthreads();
    int tx = tid & 127, cg = tid >> 7;
    for (int ci = 0; ci < 64; ci += 2) {
        int c = cg * 64 + ci;
        const float4* fa = reinterpret_cast<const float4*>(fb + c * 512);
        const float4* fbp = reinterpret_cast<const float4*>(fb + (c + 1) * 512);
        float acc0 = 0.f, acc1 = 0.f;
#pragma unroll 8
        for (int k4 = 0; k4 < 128; k4++) {
            float4 a = __ldg(&fa[k4]);
            float4 bb = __ldg(&fbp[k4]);
            int k = k4 * 4;
            float x0 = xs[tx + k], x1 = xs[tx + k + 1], x2 = xs[tx + k + 2], x3 = xs[tx + k + 3];
            acc0 += a.x * x0 + a.y * x1 + a.z * x2 + a.w * x3;
            acc1 += bb.x * x0 + bb.y * x1 + bb.z * x2 + bb.w * x3;
        }
        g_bufA[(b * NC + c) * NT + t0 + tx] = acc0;
        g_bufA[(b * NC + c + 1) * NT + t0 + tx] = acc1;
    }
}

// ---------------- residual dilated layer (GEMM 128 x 256 x T) ----------------
// h[c,t] = sum_ci W0[c,ci]*X[ci,t+o0] + W1[c,ci]*X[ci,t+o1] + bias[c]
// Y[c,t] = X[c,t] + leaky_relu(h, 0.2)
__global__ void __launch_bounds__(256, 2) k_layer(int srcIsA, int lidx,
                                                  const float* __restrict__ bias,
                                                  int o0, int o1) {
    __shared__ __align__(16) float As[32][128];
    __shared__ __align__(16) float Bs[32][128];
    const float* X = srcIsA ? g_bufA : g_bufB;
    float* Y = srcIsA ? g_bufB : g_bufA;
    int b = blockIdx.y, t0 = blockIdx.x * 128;
    int tid = threadIdx.x;
    int tx = tid & 15, ty = tid >> 4;
    int c0 = ty * 8, ta = tx * 4;
    const float* Wt = g_Wt + lidx * 32768;
    const float* Xb = X + b * NC * NT;

    float acc[8][8];
#pragma unroll
    for (int i = 0; i < 8; i++)
#pragma unroll
        for (int j = 0; j < 8; j++) acc[i][j] = 0.f;

    for (int kc = 0; kc < 256; kc += 32) {
#pragma unroll
        for (int i = 0; i < 16; i++) {
            int li = i * 256 + tid;
            As[li >> 7][li & 127] = Wt[kc * 128 + li];
        }
#pragma unroll
        for (int i = 0; i < 16; i++) {
            int li = i * 256 + tid;
            int r = li >> 7, col = li & 127;
            int k = kc + r;
            int off = (k & 1) ? o1 : o0;
            int src = t0 + col + off;
            Bs[r][col] = (src >= 0 && src < NT) ? Xb[(k >> 1) * NT + src] : 0.f;
        }
        __syncthreads();
#pragma unroll 2
        for (int kk = 0; kk < 32; kk++) {
            float4 a0 = *(const float4*)&As[kk][c0];
            float4 a1 = *(const float4*)&As[kk][c0 + 4];
            float4 b0 = *(const float4*)&Bs[kk][ta];
            float4 b1 = *(const float4*)&Bs[kk][64 + ta];
            float av[8] = {a0.x, a0.y, a0.z, a0.w, a1.x, a1.y, a1.z, a1.w};
            float bv[8] = {b0.x, b0.y, b0.z, b0.w, b1.x, b1.y, b1.z, b1.w};
#pragma unroll
            for (int i = 0; i < 8; i++)
#pragma unroll
                for (int j = 0; j < 8; j++) acc[i][j] += av[i] * bv[j];
        }
        __syncthreads();
    }
#pragma unroll
    for (int i = 0; i < 8; i++) {
        int c = c0 + i;
        float bi = bias[c];
#pragma unroll
        for (int j = 0; j < 8; j++) {
            int t = t0 + ((j < 4) ? (ta + j) : (64 + ta + j - 4));
            float h = acc[i][j] + bi;
            h = (h > 0.f) ? h : 0.2f * h;
            Y[(b * NC + c) * NT + t] = Xb[c * NT + t] + h;
        }
    }
}

// ---------------- subsampled up-projection (for threshold bootstrap) ----------------
__global__ void k_sub(const float* __restrict__ up_w, const float* __restrict__ up_b) {
    int u = blockIdx.x * 32 + threadIdx.x;
    int tsI = blockIdx.y * 8 + threadIdx.y;
    int b = blockIdx.z;
    int t = tsI * 64;
    const float* e = g_bufA + (b * NC) * NT + t;
    const float* w = up_w + u * 128;
    float acc = up_b[u];
#pragma unroll 8
    for (int c = 0; c < 128; c++) acc += __ldg(&w[c]) * __ldg(&e[c * NT]);
    g_ysub[(b * 2048 + u) * 512 + tsI] = acc;
}

__device__ __forceinline__ unsigned f2ord(float v) {
    unsigned u = __float_as_uint(v);
    return (u & 0x80000000u) ? ~u : (u | 0x80000000u);
}
__device__ __forceinline__ float ord2f(unsigned k) {
    unsigned u = (k & 0x80000000u) ? (k ^ 0x80000000u) : ~k;
    return __uint_as_float(u);
}

// ---------------- conservative threshold = ~64th largest of subsample ----------------
__global__ void k_thresh() {
    __shared__ unsigned hist[2048];
    __shared__ int s_b1, s_m;
    int b = blockIdx.x, tid = threadIdx.x;
    const float* ys = g_ysub + b * 2048 * 512;
    for (int i = tid; i < 2048; i += 1024) hist[i] = 0;
    __syncthreads();
    for (int i = tid; i < 2048 * 512; i += 1024)
        atomicAdd(&hist[f2ord(ys[i]) >> 21], 1u);
    __syncthreads();
    if (tid == 0) {
        unsigned acc = 0;
        int b1 = 0, m = 64;
        for (int i = 2047; i >= 0; i--) {
            acc += hist[i];
            if (acc >= 64) { b1 = i; m = 64 - (int)(acc - hist[i]); break; }
        }
        s_b1 = b1; s_m = m;
    }
    __syncthreads();
    int b1 = s_b1, m = s_m;
    for (int i = tid; i < 2048; i += 1024) hist[i] = 0;
    __syncthreads();
    for (int i = tid; i < 2048 * 512; i += 1024) {
        unsigned key = f2ord(ys[i]);
        if ((int)(key >> 21) == b1) atomicAdd(&hist[(key >> 10) & 2047], 1u);
    }
    __syncthreads();
    if (tid == 0) {
        unsigned acc = 0;
        int b2 = 0;
        for (int i = 2047; i >= 0; i--) {
            acc += hist[i];
            if ((int)acc >= m) { b2 = i; break; }
        }
        unsigned tk = ((unsigned)b1 << 21) | ((unsigned)b2 << 10);
        if (tk >= (1u << 10)) tk -= (1u << 10);  // one-bin safety margin
        g_thresh[b] = ord2f(tk);
        g_candCnt[b] = 0;
    }
}

// ---------------- full up-projection, emit only candidates >= threshold ----------------
__global__ void __launch_bounds__(256, 2) k_up(const float* __restrict__ up_b) {
    __shared__ __align__(16) float As[32][128];
    __shared__ __align__(16) float Bs[32][128];
    int b = blockIdx.z;
    int u0 = blockIdx.y * 128;
    int t0 = blockIdx.x * 128;
    int tid = threadIdx.x;
    int tx = tid & 15, ty = tid >> 4;
    int c0 = ty * 8, ta = tx * 4;
    const float* E = g_bufA + b * NC * NT;

    float acc[8][8];
#pragma unroll
    for (int i = 0; i < 8; i++)
#pragma unroll
        for (int j = 0; j < 8; j++) acc[i][j] = 0.f;

    for (int kc = 0; kc < 128; kc += 32) {
#pragma unroll
        for (int i = 0; i < 16; i++) {
            int li = i * 256 + tid;
            int r = li >> 7, col = li & 127;
            As[r][col] = g_upwT[(kc + r) * 2048 + u0 + col];
        }
#pragma unroll
        for (int i = 0; i < 16; i++) {
            int li = i * 256 + tid;
            int r = li >> 7, col = li & 127;
            Bs[r][col] = E[(kc + r) * NT + t0 + col];
        }
        __syncthreads();
#pragma unroll 2
        for (int kk = 0; kk < 32; kk++) {
            float4 a0 = *(const float4*)&As[kk][c0];
            float4 a1 = *(const float4*)&As[kk][c0 + 4];
            float4 b0 = *(const float4*)&Bs[kk][ta];
            float4 b1 = *(const float4*)&Bs[kk][64 + ta];
            float av[8] = {a0.x, a0.y, a0.z, a0.w, a1.x, a1.y, a1.z, a1.w};
            float bv[8] = {b0.x, b0.y, b0.z, b0.w, b1.x, b1.y, b1.z, b1.w};
#pragma unroll
            for (int i = 0; i < 8; i++)
#pragma unroll
                for (int j = 0; j < 8; j++) acc[i][j] += av[i] * bv[j];
        }
        __syncthreads();
    }
    float T0 = g_thresh[b];
#pragma unroll
    for (int i = 0; i < 8; i++) {
        int u = u0 + c0 + i;
        float bi = up_b[u];
#pragma unroll
        for (int j = 0; j < 8; j++) {
            float v = acc[i][j] + bi;
            if (v >= T0) {
                int t = t0 + ((j < 4) ? (ta + j) : (64 + ta + j - 4));
                int idx = atomicAdd(&g_candCnt[b], 1);
                if (idx < CAP) {
                    g_candVal[b * CAP + idx] = v;
                    g_candPack[b * CAP + idx] = ((unsigned)u << 16) | (unsigned)t;
                }
            }
        }
    }
}

// ---------------- exact top-64 of candidates ----------------
__global__ void k_select() {
    __shared__ unsigned long long red[256];
    int b = blockIdx.x, tid = threadIdx.x;
    int cnt = g_candCnt[b];
    if (cnt > CAP) cnt = CAP;
    unsigned long long prev = 0xFFFFFFFFFFFFFFFFull;
    for (int r = 0; r < 64; r++) {
        unsigned long long best = 0;
        for (int i = tid; i < cnt; i += 256) {
            unsigned key = f2ord(g_candVal[b * CAP + i]);
            unsigned pack = g_candPack[b * CAP + i];
            unsigned long long k64 = ((unsigned long long)key << 32) | (unsigned long long)(~pack);
            if (k64 < prev && k64 > best) best = k64;
        }
        red[tid] = best;
        __syncthreads();
        for (int s = 128; s > 0; s >>= 1) {
            if (tid < s) { if (red[tid + s] > red[tid]) red[tid] = red[tid + s]; }
            __syncthreads();
        }
        best = red[0];
        if (tid == 0) {
            unsigned key = (unsigned)(best >> 32);
            unsigned pack = ~((unsigned)best);
            g_selVal[b * 64 + r] = ord2f(key);
            g_selU[b * 64 + r] = (int)(pack >> 16);
            g_selT[b * 64 + r] = (int)(pack & 0xFFFFu);
        }
        prev = best;
        __syncthreads();
    }
}

// ---------------- down-projection: fill bias + scatter 64 columns ----------------
__global__ void k_fill(const float* __restrict__ down_b) {
    int idx = blockIdx.x * 256 + threadIdx.x;
    if (idx < NB * NC * NT) g_bufB[idx] = down_b[(idx >> 15) & 127];
}

__global__ void k_scatter(const float* __restrict__ down_w) {
    int tid = threadIdx.x;
    int b = tid >> 7, c = tid & 127;
    float* dst = g_bufB + (b * NC + c) * NT;
    for (int e = 0; e < 64; e++) {
        float v = g_selVal[b * 64 + e];
        int u = g_selU[b * 64 + e];
        int t = g_selT[b * 64 + e];
        dst[t] += down_w[c * 2048 + u] * v;
    }
}

// ---------------- transposed filterbank synthesis ----------------
// out[b,t] = sum_c sum_j fb[c,j] * dec[b,c,t+256-j], index clipped to [0,NT)
__global__ void __launch_bounds__(256) k_final(const float* __restrict__ fb,
                                               float* __restrict__ out) {
    __shared__ float fbs[8][512];
    __shared__ float ds[8][576];
    __shared__ float red[256];
    int b = blockIdx.y, t0 = blockIdx.x * 64;
    int tid = threadIdx.x;
    int tloc = tid & 63, cs = tid >> 6;
    const float* D = g_bufB + b * NC * NT;
    float acc = 0.f;
    for (int cc = 0; cc < 128; cc += 8) {
        for (int i = tid; i < 8 * 512; i += 256)
            fbs[i >> 9][i & 511] = fb[(cc + (i >> 9)) * 512 + (i & 511)];
        for (int i = tid; i < 8 * 575; i += 256) {
            int c = i / 575, w = i - c * 575;
            int g = t0 - 255 + w;
            ds[c][w] = (g >= 0 && g < NT) ? D[(cc + c) * NT + g] : 0.f;
        }
        __syncthreads();
#pragma unroll
        for (int cr = 0; cr < 2; cr++) {
            int c = cs * 2 + cr;
#pragma unroll 8
            for (int j = 0; j < 512; j++)
                acc += fbs[c][j] * ds[c][tloc + 511 - j];
        }
        __syncthreads();
    }
    red[tid] = acc;
    __syncthreads();
    if (cs == 0)
        out[b * NT + t0 + tloc] = red[tloc] + red[64 + tloc] + red[128 + tloc] + red[192 + tloc];
}

// ---------------- host driver ----------------
extern "C" void kernel_launch(void* const* d_in, const int* in_sizes, int n_in,
                              void* d_out, int out_size) {
    const float* x      = (const float*)d_in[0];
    const float* fb     = (const float*)d_in[1];
    const float* enc_w  = (const float*)d_in[2];
    const float* enc_b  = (const float*)d_in[3];
    const float* up_w   = (const float*)d_in[4];
    const float* up_b   = (const float*)d_in[5];
    const float* down_w = (const float*)d_in[6];
    const float* down_b = (const float*)d_in[7];
    const float* dec_w  = (const float*)d_in[8];
    const float* dec_b  = (const float*)d_in[9];
    float* out = (float*)d_out;

    static const int dil[6] = {1, 3, 9, 27, 81, 1};

    k_wt<<<(12 * 256 * 128 + 255) / 256, 256>>>(enc_w, dec_w);
    k_upwT<<<(128 * 2048 + 255) / 256, 256>>>(up_w);

    k_fb<<<dim3(NT / 128, NB), 256>>>(x, fb);

    // encoder: 'only-future' -> offsets (0, +d). bufA -> bufB -> bufA ...
    int srcIsA = 1;
    for (int l = 0; l < 6; l++) {
        k_layer<<<dim3(NT / 128, NB), 256>>>(srcIsA, l, enc_b + l * 128, 0, dil[l]);
        srcIsA ^= 1;
    }
    // encoder output now in bufA (6 flips -> back to A)

    k_sub<<<dim3(2048 / 32, 512 / 8, NB), dim3(32, 8)>>>(up_w, up_b);
    k_thresh<<<NB, 1024>>>();
    k_up<<<dim3(NT / 128, NU / 128, NB), 256>>>(up_b);
    k_select<<<NB, 256>>>();

    k_fill<<<(NB * NC * NT + 255) / 256, 256>>>(down_b);
    k_scatter<<<1, 256>>>(down_w);

    // decoder: 'only-past' -> offsets (-d, 0). bufB -> bufA -> bufB ...
    srcIsA = 0;
    for (int l = 0; l < 6; l++) {
        k_layer<<<dim3(NT / 128, NB), 256>>>(srcIsA, 6 + l, dec_b + l * 128, -dil[l], 0);
        srcIsA ^= 1;
    }
    // decoder output now in bufB

    k_final<<<dim3(NT / 64, NB), 256>>>(fb, out);
    (void)in_sizes; (void)n_in; (void)out_size;
}

// round 4
// speedup vs baseline: 2.1249x; 2.1249x over previous
#include <cuda_runtime.h>
#include <cstdint>

#define NB 2
#define NC 128
#define NU 2048
#define KF 512
#define NZK 64
#define NT 32768
#define NTP (NT + 512)
#define GOF 256
#define XP  (NT + 512)
#define CAP (1<<18)

static __device__ __align__(16) float g_bufA[NB*NC*NTP];
static __device__ __align__(16) float g_bufB[NB*NC*NTP];
static __device__ __align__(16) float g_Wt[12*256*128];      // [layer][k=2*ci+tap][cout]
static __device__ __align__(16) float g_upwT[128*2048];      // [c][u]
static __device__ __align__(16) float g_fbT[512*128];        // [k][c]
static __device__ __align__(16) float g_xp[NB*XP];
static __device__ float g_ysub[NB*2048*512];
static __device__ float g_thresh[NB];
static __device__ int   g_candCnt[NB];
static __device__ float g_candVal[NB*CAP];
static __device__ unsigned g_candPack[NB*CAP];
static __device__ float g_selVal[NB*NZK];
static __device__ int   g_selU[NB*NZK];
static __device__ int   g_selT[NB*NZK];
static __device__ float g_base[7*128];     // decoder steady-state per level
static __device__ int   g_act[NB*256];     // per-(batch, 128-col block) active flag

// ---------------- cp.async helpers ----------------
__device__ __forceinline__ void cp16(void* dst, const void* src) {
    unsigned d = (unsigned)__cvta_generic_to_shared(dst);
    asm volatile("cp.async.cg.shared.global [%0], [%1], 16;\n" :: "r"(d), "l"(src));
}
__device__ __forceinline__ void cp4(void* dst, const void* src) {
    unsigned d = (unsigned)__cvta_generic_to_shared(dst);
    asm volatile("cp.async.ca.shared.global [%0], [%1], 4;\n" :: "r"(d), "l"(src));
}
#define CP_COMMIT() asm volatile("cp.async.commit_group;\n")
#define CP_WAIT1()  asm volatile("cp.async.wait_group 1;\n")
#define CP_WAIT0()  asm volatile("cp.async.wait_group 0;\n")

// ---------------- weight / input prep ----------------
__global__ void k_wt(const float* __restrict__ enc_w, const float* __restrict__ dec_w) {
    int idx = blockIdx.x * 256 + threadIdx.x;
    if (idx >= 12 * 256 * 128) return;
    int l = idx / 32768;
    int r = idx - l * 32768;
    int k = r >> 7, c = r & 127;
    int ci = k >> 1, tap = k & 1;
    const float* w = (l < 6) ? (enc_w + l * 32768) : (dec_w + (l - 6) * 32768);
    g_Wt[idx] = w[(c * 128 + ci) * 2 + tap];
}

__global__ void k_upwT(const float* __restrict__ up_w) {
    int idx = blockIdx.x * 256 + threadIdx.x;
    if (idx >= 128 * 2048) return;
    int c = idx >> 11, u = idx & 2047;
    g_upwT[idx] = up_w[u * 128 + c];
}

__global__ void k_fbT(const float* __restrict__ fb) {
    int idx = blockIdx.x * 256 + threadIdx.x;
    if (idx >= 512 * 128) return;
    int k = idx >> 7, c = idx & 127;
    g_fbT[idx] = fb[c * 512 + k];
}

__global__ void k_xp(const float* __restrict__ x) {
    int idx = blockIdx.x * 256 + threadIdx.x;
    if (idx >= NB * XP) return;
    int b = idx / XP, w = idx - b * XP;
    g_xp[idx] = (w >= GOF && w < NT + GOF) ? x[b * NT + (w - GOF)] : 0.f;
}

__global__ void k_guard() {
    int idx = blockIdx.x * 256 + threadIdx.x;
    int half = NB * NC * 512;
    if (idx >= 2 * half) return;
    float* buf = (idx < half) ? g_bufA : g_bufB;
    int r = (idx < half) ? idx : idx - half;
    int row = r >> 9, w = r & 511;
    int pos = (w < 256) ? w : (NT + 256 + (w - 256));
    buf[row * NTP + pos] = 0.f;
}

// ---------------- filterbank analysis as GEMM (double-buffered) ----------------
__global__ void __launch_bounds__(256, 2) k_fb() {
    __shared__ __align__(16) float As[2][16][128];
    __shared__ __align__(16) float Bs[2][16][128];
    int b = blockIdx.y, t0 = blockIdx.x * 128;
    int tid = threadIdx.x;
    int tx = tid & 15, ty = tid >> 4;
    int c0 = ty * 8, ta = tx * 4;
    const float* xb = g_xp + b * XP;

    float acc[8][8];
#pragma unroll
    for (int i = 0; i < 8; i++)
#pragma unroll
        for (int j = 0; j < 8; j++) acc[i][j] = 0.f;

#define FB_LOAD(st, kc) {                                                    \
    _Pragma("unroll")                                                        \
    for (int i = 0; i < 2; i++) {                                            \
        int li = i * 256 + tid;                                              \
        int r = li >> 5, c4 = (li & 31) * 4;                                 \
        cp16(&As[st][r][c4], g_fbT + ((kc) + r) * 128 + c4);                 \
    }                                                                        \
    _Pragma("unroll")                                                        \
    for (int i = 0; i < 8; i++) {                                            \
        int li = i * 256 + tid;                                              \
        int r = li >> 7, col = li & 127;                                     \
        cp4(&Bs[st][r][col], xb + t0 + col + (kc) + r);                      \
    }                                                                        \
    CP_COMMIT(); }

    FB_LOAD(0, 0);
    for (int ch = 0; ch < 32; ch++) {
        if (ch + 1 < 32) { FB_LOAD((ch + 1) & 1, (ch + 1) * 16); CP_WAIT1(); }
        else CP_WAIT0();
        __syncthreads();
        int s = ch & 1;
#pragma unroll
        for (int kk = 0; kk < 16; kk++) {
            float4 a0 = *(const float4*)&As[s][kk][c0];
            float4 a1 = *(const float4*)&As[s][kk][c0 + 4];
            float4 b0 = *(const float4*)&Bs[s][kk][ta];
            float4 b1 = *(const float4*)&Bs[s][kk][64 + ta];
            float av[8] = {a0.x, a0.y, a0.z, a0.w, a1.x, a1.y, a1.z, a1.w};
            float bv[8] = {b0.x, b0.y, b0.z, b0.w, b1.x, b1.y, b1.z, b1.w};
#pragma unroll
            for (int i = 0; i < 8; i++)
#pragma unroll
                for (int j = 0; j < 8; j++) acc[i][j] += av[i] * bv[j];
        }
        __syncthreads();
    }
#undef FB_LOAD
#pragma unroll
    for (int i = 0; i < 8; i++) {
        int c = c0 + i;
#pragma unroll
        for (int j = 0; j < 8; j++) {
            int t = t0 + ((j < 4) ? (ta + j) : (64 + ta + j - 4));
            g_bufA[(b * NC + c) * NTP + GOF + t] = acc[i][j];
        }
    }
}

// ---------------- residual dilated layer (double-buffered, optional sparsity) ----------------
__global__ void __launch_bounds__(256, 2) k_layer(int srcIsA, int lidx,
                                                  const float* __restrict__ bias,
                                                  int o0, int o1, int sparse, int lvl) {
    __shared__ __align__(16) float As[2][16][128];
    __shared__ __align__(16) float Bs[2][16][128];
    const float* X = srcIsA ? g_bufA : g_bufB;
    float* Y = srcIsA ? g_bufB : g_bufA;
    int b = blockIdx.y, blk = blockIdx.x, t0 = blk * 128;
    int tid = threadIdx.x;
    int tx = tid & 15, ty = tid >> 4;
    int c0 = ty * 8, ta = tx * 4;

    if (sparse && !g_act[b * 256 + blk]) {
        // entire block provably at steady-state: store next-level base, done.
#pragma unroll
        for (int i = 0; i < 8; i++) {
            float v = g_base[(lvl + 1) * 128 + c0 + i];
#pragma unroll
            for (int j = 0; j < 8; j++) {
                int t = t0 + ((j < 4) ? (ta + j) : (64 + ta + j - 4));
                Y[(b * NC + c0 + i) * NTP + GOF + t] = v;
            }
        }
        return;
    }

    const float* Wt = g_Wt + lidx * 32768;
    const float* Xb = X + b * NC * NTP;
    int dOff = o1 - o0;

    float acc[8][8];
#pragma unroll
    for (int i = 0; i < 8; i++)
#pragma unroll
        for (int j = 0; j < 8; j++) acc[i][j] = 0.f;

#define LY_LOAD(st, kc) {                                                    \
    _Pragma("unroll")                                                        \
    for (int i = 0; i < 2; i++) {                                            \
        int li = i * 256 + tid;                                              \
        int r = li >> 5, c4 = (li & 31) * 4;                                 \
        cp16(&As[st][r][c4], Wt + ((kc) + r) * 128 + c4);                    \
    }                                                                        \
    _Pragma("unroll")                                                        \
    for (int i = 0; i < 8; i++) {                                            \
        int li = i * 256 + tid;                                              \
        int r = li >> 7, col = li & 127;                                     \
        int k = (kc) + r;                                                    \
        int off = o0 + (k & 1) * dOff;                                       \
        cp4(&Bs[st][r][col], Xb + (k >> 1) * NTP + GOF + t0 + col + off);    \
    }                                                                        \
    CP_COMMIT(); }

    LY_LOAD(0, 0);
    for (int ch = 0; ch < 16; ch++) {
        if (ch + 1 < 16) { LY_LOAD((ch + 1) & 1, (ch + 1) * 16); CP_WAIT1(); }
        else CP_WAIT0();
        __syncthreads();
        int s = ch & 1;
#pragma unroll
        for (int kk = 0; kk < 16; kk++) {
            float4 a0 = *(const float4*)&As[s][kk][c0];
            float4 a1 = *(const float4*)&As[s][kk][c0 + 4];
            float4 b0 = *(const float4*)&Bs[s][kk][ta];
            float4 b1 = *(const float4*)&Bs[s][kk][64 + ta];
            float av[8] = {a0.x, a0.y, a0.z, a0.w, a1.x, a1.y, a1.z, a1.w};
            float bv[8] = {b0.x, b0.y, b0.z, b0.w, b1.x, b1.y, b1.z, b1.w};
#pragma unroll
            for (int i = 0; i < 8; i++)
#pragma unroll
                for (int j = 0; j < 8; j++) acc[i][j] += av[i] * bv[j];
        }
        __syncthreads();
    }
#undef LY_LOAD
#pragma unroll
    for (int i = 0; i < 8; i++) {
        int c = c0 + i;
        float bi = bias[c];
        const float* xr = Xb + c * NTP + GOF;
        float* yr = Y + (b * NC + c) * NTP + GOF;
#pragma unroll
        for (int j = 0; j < 8; j++) {
            int t = t0 + ((j < 4) ? (ta + j) : (64 + ta + j - 4));
            float h = acc[i][j] + bi;
            h = (h > 0.f) ? h : 0.2f * h;
            yr[t] = xr[t] + h;
        }
    }
}

// ---------------- subsampled up-projection (coalesced via upwT) ----------------
__global__ void __launch_bounds__(256) k_sub(const float* __restrict__ up_b) {
    __shared__ float es[16][128];
    int b = blockIdx.z;
    int u = blockIdx.x * 256 + threadIdx.x;
    int ts0 = blockIdx.y * 16;
    const float* E = g_bufA + b * NC * NTP + GOF;
    for (int i = threadIdx.x; i < 16 * 128; i += 256) {
        int tsl = i >> 7, c = i & 127;
        es[tsl][c] = E[c * NTP + (ts0 + tsl) * 64];
    }
    __syncthreads();
    float acc[16];
    float bi = up_b[u];
#pragma unroll
    for (int j = 0; j < 16; j++) acc[j] = bi;
    for (int c = 0; c < 128; c++) {
        float w = g_upwT[c * 2048 + u];
#pragma unroll
        for (int j = 0; j < 16; j++) acc[j] += w * es[j][c];
    }
#pragma unroll
    for (int j = 0; j < 16; j++)
        g_ysub[(b * 2048 + u) * 512 + ts0 + j] = acc[j];
}

__device__ __forceinline__ unsigned f2ord(float v) {
    unsigned u = __float_as_uint(v);
    return (u & 0x80000000u) ? ~u : (u | 0x80000000u);
}
__device__ __forceinline__ float ord2f(unsigned k) {
    unsigned u = (k & 0x80000000u) ? (k ^ 0x80000000u) : ~k;
    return __uint_as_float(u);
}

// ---------------- conservative threshold = ~64th largest of subsample ----------------
__global__ void k_thresh() {
    __shared__ unsigned hist[2048];
    __shared__ int s_b1, s_m;
    int b = blockIdx.x, tid = threadIdx.x;
    const float* ys = g_ysub + b * 2048 * 512;
    for (int i = tid; i < 2048; i += 1024) hist[i] = 0;
    __syncthreads();
    for (int i = tid; i < 2048 * 512; i += 1024)
        atomicAdd(&hist[f2ord(ys[i]) >> 21], 1u);
    __syncthreads();
    if (tid == 0) {
        unsigned acc = 0;
        int b1 = 0, m = 64;
        for (int i = 2047; i >= 0; i--) {
            acc += hist[i];
            if (acc >= 64) { b1 = i; m = 64 - (int)(acc - hist[i]); break; }
        }
        s_b1 = b1; s_m = m;
    }
    __syncthreads();
    int b1 = s_b1, m = s_m;
    for (int i = tid; i < 2048; i += 1024) hist[i] = 0;
    __syncthreads();
    for (int i = tid; i < 2048 * 512; i += 1024) {
        unsigned key = f2ord(ys[i]);
        if ((int)(key >> 21) == b1) atomicAdd(&hist[(key >> 10) & 2047], 1u);
    }
    __syncthreads();
    if (tid == 0) {
        unsigned acc = 0;
        int b2 = 0;
        for (int i = 2047; i >= 0; i--) {
            acc += hist[i];
            if ((int)acc >= m) { b2 = i; break; }
        }
        unsigned tk = ((unsigned)b1 << 21) | ((unsigned)b2 << 10);
        if (tk >= (1u << 10)) tk -= (1u << 10);  // one-bin safety margin
        g_thresh[b] = ord2f(tk);
        g_candCnt[b] = 0;
    }
}

// ---------------- full up-projection (double-buffered), emit candidates ----------------
__global__ void __launch_bounds__(256, 2) k_up(const float* __restrict__ up_b) {
    __shared__ __align__(16) float As[2][16][128];
    __shared__ __align__(16) float Bs[2][16][128];
    int b = blockIdx.z;
    int u0 = blockIdx.y * 128;
    int t0 = blockIdx.x * 128;
    int tid = threadIdx.x;
    int tx = tid & 15, ty = tid >> 4;
    int c0 = ty * 8, ta = tx * 4;
    const float* E = g_bufA + b * NC * NTP + GOF;

    float acc[8][8];
#pragma unroll
    for (int i = 0; i < 8; i++)
#pragma unroll
        for (int j = 0; j < 8; j++) acc[i][j] = 0.f;

#define UP_LOAD(st, kc) {                                                    \
    _Pragma("unroll")                                                        \
    for (int i = 0; i < 2; i++) {                                            \
        int li = i * 256 + tid;                                              \
        int r = li >> 5, c4 = (li & 31) * 4;                                 \
        cp16(&As[st][r][c4], g_upwT + ((kc) + r) * 2048 + u0 + c4);          \
        cp16(&Bs[st][r][c4], E + ((kc) + r) * NTP + t0 + c4);                \
    }                                                                        \
    CP_COMMIT(); }

    UP_LOAD(0, 0);
    for (int ch = 0; ch < 8; ch++) {
        if (ch + 1 < 8) { UP_LOAD((ch + 1) & 1, (ch + 1) * 16); CP_WAIT1(); }
        else CP_WAIT0();
        __syncthreads();
        int s = ch & 1;
#pragma unroll
        for (int kk = 0; kk < 16; kk++) {
            float4 a0 = *(const float4*)&As[s][kk][c0];
            float4 a1 = *(const float4*)&As[s][kk][c0 + 4];
            float4 b0 = *(const float4*)&Bs[s][kk][ta];
            float4 b1 = *(const float4*)&Bs[s][kk][64 + ta];
            float av[8] = {a0.x, a0.y, a0.z, a0.w, a1.x, a1.y, a1.z, a1.w};
            float bv[8] = {b0.x, b0.y, b0.z, b0.w, b1.x, b1.y, b1.z, b1.w};
#pragma unroll
            for (int i = 0; i < 8; i++)
#pragma unroll
                for (int j = 0; j < 8; j++) acc[i][j] += av[i] * bv[j];
        }
        __syncthreads();
    }
#undef UP_LOAD
    float T0 = g_thresh[b];
#pragma unroll
    for (int i = 0; i < 8; i++) {
        int u = u0 + c0 + i;
        float bi = up_b[u];
#pragma unroll
        for (int j = 0; j < 8; j++) {
            float v = acc[i][j] + bi;
            if (v >= T0) {
                int t = t0 + ((j < 4) ? (ta + j) : (64 + ta + j - 4));
                int idx = atomicAdd(&g_candCnt[b], 1);
                if (idx < CAP) {
                    g_candVal[b * CAP + idx] = v;
                    g_candPack[b * CAP + idx] = ((unsigned)u << 16) | (unsigned)t;
                }
            }
        }
    }
}

// ---------------- exact top-64 of candidates ----------------
__global__ void k_select() {
    __shared__ unsigned long long red[256];
    int b = blockIdx.x, tid = threadIdx.x;
    int cnt = g_candCnt[b];
    if (cnt > CAP) cnt = CAP;
    unsigned long long prev = 0xFFFFFFFFFFFFFFFFull;
    for (int r = 0; r < 64; r++) {
        unsigned long long best = 0;
        for (int i = tid; i < cnt; i += 256) {
            unsigned key = f2ord(g_candVal[b * CAP + i]);
            unsigned pack = g_candPack[b * CAP + i];
            unsigned long long k64 = ((unsigned long long)key << 32) | (unsigned long long)(~pack);
            if (k64 < prev && k64 > best) best = k64;
        }
        red[tid] = best;
        __syncthreads();
        for (int s = 128; s > 0; s >>= 1) {
            if (tid < s) { if (red[tid + s] > red[tid]) red[tid] = red[tid + s]; }
            __syncthreads();
        }
        best = red[0];
        if (tid == 0) {
            unsigned key = (unsigned)(best >> 32);
            unsigned pack = ~((unsigned)best);
            g_selVal[b * 64 + r] = ord2f(key);
            g_selU[b * 64 + r] = (int)(pack >> 16);
            g_selT[b * 64 + r] = (int)(pack & 0xFFFFu);
        }
        prev = best;
        __syncthreads();
    }
}

// ---------------- decoder steady-state baselines ----------------
__global__ void k_base(const float* __restrict__ down_b, const float* __restrict__ dec_b) {
    __shared__ float cur[128];
    int c = threadIdx.x;
    cur[c] = down_b[c];
    g_base[c] = cur[c];
    __syncthreads();
    for (int l = 0; l < 6; l++) {
        const float* Wt = g_Wt + (6 + l) * 32768;
        float h = dec_b[l * 128 + c];
        for (int ci = 0; ci < 128; ci++)
            h += (Wt[(2 * ci) * 128 + c] + Wt[(2 * ci + 1) * 128 + c]) * cur[ci];
        h = (h > 0.f) ? h : 0.2f * h;
        float nv = cur[c] + h;
        __syncthreads();
        cur[c] = nv;
        g_base[(l + 1) * 128 + c] = nv;
        __syncthreads();
    }
}

// ---------------- decoder active-block flags ----------------
__global__ void k_flags() {
    int idx = threadIdx.x;
    if (idx >= NB * 256) return;
    int b = idx >> 8, blk = idx & 255;
    int lo = blk * 128, hi = lo + 127;
    int act = (lo < 123) ? 1 : 0;
    for (int e = 0; e < 64; e++) {
        int s = g_selT[b * 64 + e];
        if (s <= hi && s + 122 >= lo) act = 1;
    }
    g_act[idx] = act;
}

// ---------------- down-projection: fill bias + scatter 64 columns ----------------
__global__ void k_fill(const float* __restrict__ down_b) {
    int idx = blockIdx.x * 256 + threadIdx.x;
    if (idx >= NB * NC * NT) return;
    int row = idx >> 15, t = idx & 32767;
    g_bufB[row * NTP + GOF + t] = down_b[row & 127];
}

__global__ void k_scatter(const float* __restrict__ down_w) {
    int tid = threadIdx.x;
    int b = tid >> 7, c = tid & 127;
    float* dst = g_bufB + (b * NC + c) * NTP + GOF;
    for (int e = 0; e < 64; e++) {
        float v = g_selVal[b * 64 + e];
        int u = g_selU[b * 64 + e];
        int t = g_selT[b * 64 + e];
        dst[t] += down_w[c * 2048 + u] * v;
    }
}

// ---------------- transposed filterbank synthesis (sliding window) ----------------
__global__ void __launch_bounds__(256) k_final(const float* __restrict__ fb,
                                               float* __restrict__ out) {
    __shared__ __align__(16) float fbs[8][512];
    __shared__ __align__(16) float ds[8][640];
    __shared__ float red[8][128];
    int b = blockIdx.y, t0 = blockIdx.x * 128;
    int tid = threadIdx.x;
    int lane = tid & 31, cs = tid >> 5;
    const float* D = g_bufB + b * NC * NTP + GOF;

    float acc[4] = {0.f, 0.f, 0.f, 0.f};
    for (int cc = cs; cc < 128; cc += 8) {
        const float* fr = fb + cc * 512;
#pragma unroll
        for (int i = 0; i < 16; i++) {
            int w = lane + 32 * i;
            fbs[cs][w] = fr[511 - w];   // flipped filter
        }
        const float* Dr = D + cc * NTP + t0 - 255;
#pragma unroll
        for (int i = 0; i < 20; i++) {
            int w = lane + 32 * i;
            if (w < 639) ds[cs][w] = Dr[w];
        }
        __syncwarp();
        float w0 = ds[cs][lane * 4 + 0];
        float w1 = ds[cs][lane * 4 + 1];
        float w2 = ds[cs][lane * 4 + 2];
        float w3 = ds[cs][lane * 4 + 3];
#pragma unroll 4
        for (int k = 0; k < 512; k += 4) {
            float4 f = *(const float4*)&fbs[cs][k];
            float4 n = *(const float4*)&ds[cs][lane * 4 + k + 4];
            acc[0] += f.x * w0; acc[1] += f.x * w1; acc[2] += f.x * w2; acc[3] += f.x * w3;
            acc[0] += f.y * w1; acc[1] += f.y * w2; acc[2] += f.y * w3; acc[3] += f.y * n.x;
            acc[0] += f.z * w2; acc[1] += f.z * w3; acc[2] += f.z * n.x; acc[3] += f.z * n.y;
            acc[0] += f.w * w3; acc[1] += f.w * n.x; acc[2] += f.w * n.y; acc[3] += f.w * n.z;
            w0 = n.x; w1 = n.y; w2 = n.z; w3 = n.w;
        }
        __syncwarp();
    }
#pragma unroll
    for (int j = 0; j < 4; j++) red[cs][lane * 4 + j] = acc[j];
    __syncthreads();
    if (tid < 128) {
        float s = 0.f;
#pragma unroll
        for (int g = 0; g < 8; g++) s += red[g][tid];
        out[b * NT + t0 + tid] = s;
    }
}

// ---------------- host driver ----------------
extern "C" void kernel_launch(void* const* d_in, const int* in_sizes, int n_in,
                              void* d_out, int out_size) {
    const float* x      = (const float*)d_in[0];
    const float* fb     = (const float*)d_in[1];
    const float* enc_w  = (const float*)d_in[2];
    const float* enc_b  = (const float*)d_in[3];
    const float* up_w   = (const float*)d_in[4];
    const float* up_b   = (const float*)d_in[5];
    const float* down_w = (const float*)d_in[6];
    const float* down_b = (const float*)d_in[7];
    const float* dec_w  = (const float*)d_in[8];
    const float* dec_b  = (const float*)d_in[9];
    float* out = (float*)d_out;

    static const int dil[6] = {1, 3, 9, 27, 81, 1};

    k_wt<<<(12 * 256 * 128 + 255) / 256, 256>>>(enc_w, dec_w);
    k_upwT<<<(128 * 2048 + 255) / 256, 256>>>(up_w);
    k_fbT<<<(512 * 128 + 255) / 256, 256>>>(fb);
    k_xp<<<(NB * XP + 255) / 256, 256>>>(x);
    k_guard<<<(2 * NB * NC * 512 + 255) / 256, 256>>>();

    k_fb<<<dim3(NT / 128, NB), 256>>>();

    // encoder: 'only-future' -> offsets (0, +d)
    int srcIsA = 1;
    for (int l = 0; l < 6; l++) {
        k_layer<<<dim3(NT / 128, NB), 256>>>(srcIsA, l, enc_b + l * 128, 0, dil[l], 0, 0);
        srcIsA ^= 1;
    }
    // encoder output in bufA

    k_sub<<<dim3(NU / 256, 512 / 16, NB), 256>>>(up_b);
    k_thresh<<<NB, 1024>>>();
    k_up<<<dim3(NT / 128, NU / 128, NB), 256>>>(up_b);
    k_select<<<NB, 256>>>();

    k_base<<<1, 128>>>(down_b, dec_b);
    k_flags<<<1, 512>>>();
    k_fill<<<(NB * NC * NT + 255) / 256, 256>>>(down_b);
    k_scatter<<<1, 256>>>(down_w);

    // decoder: 'only-past' -> offsets (-d, 0), sparse block-skip
    srcIsA = 0;
    for (int l = 0; l < 6; l++) {
        k_layer<<<dim3(NT / 128, NB), 256>>>(srcIsA, 6 + l, dec_b + l * 128, -dil[l], 0, 1, l);
        srcIsA ^= 1;
    }
    // decoder output in bufB

    k_final<<<dim3(NT / 128, NB), 256>>>(fb, out);
    (void)in_sizes; (void)n_in; (void)out_size;
}